// round 12
// baseline (speedup 1.0000x reference)
#include <cuda_runtime.h>
#include <cuda_bf16.h>
#include <cstdint>

#define LEN_M   131328
#define D_H     256
#define N_MC    64
#define DDP1    513
#define NROWS   4096
#define NCOL    512        // interleaved: col 2h = A_h (m), 2h+1 = B_h (s)
#define KP      512        // MMA K (col 512 handled as rank-1 update)
#define NCHUNK  8          // 512 / 64
#define BKB     128        // bytes per smem row (64 bf16) = SW128 atom

// -------- persistent scratch (no allocs allowed) ---------------------------
__device__ __align__(128) __nv_bfloat16 g_xh[NROWS * KP];
__device__ __align__(128) __nv_bfloat16 g_xl[NROWS * KP];
__device__ __align__(128) __nv_bfloat16 g_bh[NCOL * KP];   // row 2h=m_h, 2h+1=s_h
__device__ __align__(128) __nv_bfloat16 g_bl[NCOL * KP];
__device__ __align__(128) float g_x512[NROWS];
__device__ __align__(128) float g_w512[NCOL];              // interleaved m/s
__device__ __align__(128) float g_P[4 * NROWS * N_MC];     // per-colblock partials

// -------- PTX helpers -------------------------------------------------------
__device__ __forceinline__ uint32_t s2u(const void* p) {
    uint32_t a;
    asm("{ .reg .u64 t; cvta.to.shared.u64 t, %1; cvt.u32.u64 %0, t; }"
        : "=r"(a) : "l"(p));
    return a;
}
#define SW128(o) ((o) ^ (((o) >> 3) & 0x70))

#define LDSM_X4(r, a)                                                         \
    asm volatile("ldmatrix.sync.aligned.m8n8.x4.shared.b16 {%0,%1,%2,%3}, [%4];" \
        : "=r"((r)[0]), "=r"((r)[1]), "=r"((r)[2]), "=r"((r)[3]) : "r"(a))

#define MMA16816(d, a, b)                                                     \
    asm volatile("mma.sync.aligned.m16n8k16.row.col.f32.bf16.bf16.f32 "       \
        "{%0,%1,%2,%3}, {%4,%5,%6,%7}, {%8,%9}, {%0,%1,%2,%3};"               \
        : "+f"((d)[0]), "+f"((d)[1]), "+f"((d)[2]), "+f"((d)[3])              \
        : "r"((a)[0]), "r"((a)[1]), "r"((a)[2]), "r"((a)[3]),                 \
          "r"((b)[0]), "r"((b)[1]))

__device__ __forceinline__ uint16_t bfbits(float f) {
    __nv_bfloat16 b = __float2bfloat16(f);
    return *(uint16_t*)&b;
}
__device__ __forceinline__ float bf2f(uint16_t u) {
    __nv_bfloat16 b = *(__nv_bfloat16*)&u;
    return __bfloat162float(b);
}

typedef unsigned long long ull;
union F2U { float2 f; ull u; };
__device__ __forceinline__ ull fma2(ull a, ull b, ull c) {
    ull r; asm("fma.rn.f32x2 %0, %1, %2, %3;" : "=l"(r) : "l"(a), "l"(b), "l"(c));
    return r;
}
__device__ __forceinline__ ull pk2(float x, float y) {
    ull r; asm("mov.b64 %0, {%1,%2};" : "=l"(r) : "f"(x), "f"(y)); return r;
}

// -------- Kernel 1: fused prep (ONE launch) ---------------------------------
// blocks 0..127 : weights d = 4b..4b+3 (smem transpose, 10KB smem)
// block  128    : weight row d = 512
// blocks 129..  : x rows (2 per block) -> bf16 hi/lo, uint2 stores
#define DCHUNK 4
#define XBLK0  129

__global__ __launch_bounds__(256) void prep_all(
        const float* __restrict__ params, const float* __restrict__ x,
        float* __restrict__ out_m, float* __restrict__ out_v) {
    const int b   = blockIdx.x;
    const int tid = threadIdx.x;

    if (b < 128) {
        __shared__ uint16_t tmh[256][DCHUNK + 1];
        __shared__ uint16_t tml[256][DCHUNK + 1];
        __shared__ uint16_t tsh[256][DCHUNK + 1];
        __shared__ uint16_t tsl[256][DCHUNK + 1];
        const int h = tid;
        #pragma unroll
        for (int j = 0; j < DCHUNK; j++) {
            int d = b * DCHUNK + j;
            int i = d * 256 + h;
            float m = params[i];                       // coalesced
            float v = fmaxf(params[LEN_M + i], 0.0f) + 1e-6f;
            float s = sqrtf(v);
            out_m[i] = m;
            out_v[i] = v;
            uint16_t mh = bfbits(m);
            uint16_t sh = bfbits(s);
            tmh[h][j] = mh;  tml[h][j] = bfbits(m - bf2f(mh));
            tsh[h][j] = sh;  tsl[h][j] = bfbits(s - bf2f(sh));
        }
        __syncthreads();
        const int colB = b * DCHUNK;
        auto pack = [&](uint16_t (*t)[DCHUNK + 1], int hh) -> uint2 {
            uint2 w;
            w.x = (uint32_t)t[hh][0] | ((uint32_t)t[hh][1] << 16);
            w.y = (uint32_t)t[hh][2] | ((uint32_t)t[hh][3] << 16);
            return w;
        };
        #pragma unroll
        for (int rr = 0; rr < 2; rr++) {               // rows tid, tid+256
            int r  = tid + rr * 256;
            int hh = r >> 1;
            uint2 wh = (r & 1) ? pack(tsh, hh) : pack(tmh, hh);
            uint2 wl = (r & 1) ? pack(tsl, hh) : pack(tml, hh);
            *(uint2*)(g_bh + (size_t)r * KP + colB) = wh;
            *(uint2*)(g_bl + (size_t)r * KP + colB) = wl;
        }
    } else if (b == 128) {
        const int h = tid;                              // d = 512 row
        int i = 512 * 256 + h;
        float m = params[i];
        float v = fmaxf(params[LEN_M + i], 0.0f) + 1e-6f;
        out_m[i] = m;
        out_v[i] = v;
        g_w512[2 * h]     = m;
        g_w512[2 * h + 1] = sqrtf(v);
    } else {
        const int r  = tid >> 7;            // 0..1
        const int t  = tid & 127;
        const int n  = (b - XBLK0) * 2 + r;
        const size_t base = (size_t)n * DDP1;
        float v0 = x[base + 4 * t + 0];
        float v1 = x[base + 4 * t + 1];
        float v2 = x[base + 4 * t + 2];
        float v3 = x[base + 4 * t + 3];
        uint16_t h0 = bfbits(v0), h1 = bfbits(v1), h2 = bfbits(v2), h3 = bfbits(v3);
        uint2 hp, lp;
        hp.x = (uint32_t)h0 | ((uint32_t)h1 << 16);
        hp.y = (uint32_t)h2 | ((uint32_t)h3 << 16);
        lp.x = (uint32_t)bfbits(v0 - bf2f(h0)) | ((uint32_t)bfbits(v1 - bf2f(h1)) << 16);
        lp.y = (uint32_t)bfbits(v2 - bf2f(h2)) | ((uint32_t)bfbits(v3 - bf2f(h3)) << 16);
        ((uint2*)g_xh)[n * 128 + t] = hp;
        ((uint2*)g_xl)[n * 128 + t] = lp;
        if (t == 0) g_x512[n] = x[base + 512];
    }
}

// -------- Kernel 2: HMMA GEMM + FUSED MC epilogue ---------------------------
// grid (4, 32): tile 128(M) x 128(N interleaved = 64 h). 8 warps 2(M)x4(N).
// 3-stage cp.async pipeline. Partials -> g_P (no atomics, deterministic).
#define TILE_B   16384
#define CHSET_B  (4 * TILE_B)
#define NSTAGE   3
#define GSMEM    (1024 + NSTAGE * CHSET_B)
#define ABSTRIDE 132

__global__ __launch_bounds__(256, 1) void gemm_fused(const float* __restrict__ W1,
                                                     const float* __restrict__ eps) {
    extern __shared__ __align__(1024) char smem[];
    const uint32_t sb = s2u(smem);
    float* sw512 = (float*)smem;              // [0,512): 128 floats (interleaved)
    float* sW1   = (float*)(smem + 512);      // 64 floats W1[hBase+1 ..]
    float* sEps  = (float*)(smem + 768);      // 64 floats
    const uint32_t TB = sb + 1024;

    const int tid  = threadIdx.x;
    const int lane = tid & 31;
    const int warp = tid >> 5;
    const int wm = warp >> 2;                 // 0..1
    const int wn = warp & 3;                  // 0..3
    const int rowBase = blockIdx.y * 128;
    const int colBase = blockIdx.x * 128;
    const int hBase   = blockIdx.x * 64;

    if (tid < 128)                  sw512[tid]       = g_w512[colBase + tid];
    else if (tid < 192)             sW1[tid - 128]   = W1[hBase + (tid - 128) + 1];
    else                            sEps[tid - 192]  = eps[tid - 192];

    float acc[4][4][4];
    #pragma unroll
    for (int mi = 0; mi < 4; mi++)
        #pragma unroll
        for (int nj = 0; nj < 4; nj++)
            #pragma unroll
            for (int q = 0; q < 4; q++)
                acc[mi][nj][q] = 0.0f;

    auto issue_chunk = [&](int c, int buf) {
        const uint32_t tb = TB + buf * CHSET_B;
        #pragma unroll
        for (int t = 0; t < 4; t++) {
            const char* gbase = (t == 0) ? (const char*)g_xh
                              : (t == 1) ? (const char*)g_xl
                              : (t == 2) ? (const char*)g_bh
                                         : (const char*)g_bl;
            const int rbase = (t < 2) ? rowBase : colBase;
            #pragma unroll
            for (int i = 0; i < 4; i++) {
                int q = tid + i * 256;
                int r = q >> 3, s = q & 7;
                const char* gp = gbase + (size_t)(rbase + r) * (KP * 2)
                               + c * BKB + s * 16;
                uint32_t sp = tb + t * TILE_B + SW128(r * BKB + s * 16);
                asm volatile("cp.async.cg.shared.global [%0], [%1], 16;"
                             :: "r"(sp), "l"(gp));
            }
        }
        asm volatile("cp.async.commit_group;" ::: "memory");
    };

    issue_chunk(0, 0);
    issue_chunk(1, 1);

    for (int c = 0; c < NCHUNK; c++) {
        const int buf = c % NSTAGE;

        if (c < NCHUNK - 1) {
            asm volatile("cp.async.wait_group 1;" ::: "memory");
        } else {
            asm volatile("cp.async.wait_group 0;" ::: "memory");
        }
        __syncthreads();
        if (c + 2 < NCHUNK)
            issue_chunk(c + 2, (c + 2) % NSTAGE);

        const uint32_t Ah = TB + buf * CHSET_B;
        const uint32_t Al = Ah + TILE_B;
        const uint32_t Bh = Al + TILE_B;
        const uint32_t Bl = Bh + TILE_B;

        #pragma unroll
        for (int s = 0; s < 4; s++) {
            const int k0 = s * 16;
            uint32_t ah[4][4], al[4][4], bhf[4][2], blf[4][2];

            #pragma unroll
            for (int mi = 0; mi < 4; mi++) {
                int row = wm * 64 + mi * 16 + (lane & 15);
                int col = k0 + ((lane >> 4) << 3);
                uint32_t off = SW128(row * BKB + col * 2);
                LDSM_X4(ah[mi], Ah + off);
                LDSM_X4(al[mi], Al + off);
            }
            #pragma unroll
            for (int p = 0; p < 2; p++) {
                int row = wn * 32 + p * 16 + (lane & 7) + ((lane & 16) >> 1);
                int col = k0 + (lane & 8);
                uint32_t off = SW128(row * BKB + col * 2);
                uint32_t r[4];
                LDSM_X4(r, Bh + off);
                bhf[p * 2][0] = r[0]; bhf[p * 2][1] = r[1];
                bhf[p * 2 + 1][0] = r[2]; bhf[p * 2 + 1][1] = r[3];
                LDSM_X4(r, Bl + off);
                blf[p * 2][0] = r[0]; blf[p * 2][1] = r[1];
                blf[p * 2 + 1][0] = r[2]; blf[p * 2 + 1][1] = r[3];
            }

            #pragma unroll
            for (int mi = 0; mi < 4; mi++)
                #pragma unroll
                for (int nj = 0; nj < 4; nj++) {
                    MMA16816(acc[mi][nj], ah[mi], bhf[nj]);
                    MMA16816(acc[mi][nj], ah[mi], blf[nj]);
                    MMA16816(acc[mi][nj], al[mi], bhf[nj]);
                }
        }
    }

    // ---- stage (a,b) pairs into smem (reuse pipeline region) ----
    float xv[8];
    #pragma unroll
    for (int mi = 0; mi < 4; mi++) {
        int r = rowBase + wm * 64 + mi * 16 + (lane >> 2);
        xv[2 * mi]     = g_x512[r];
        xv[2 * mi + 1] = g_x512[r + 8];
    }
    __syncthreads();                     // all MMA smem reads done

    float* AB = (float*)(smem + 1024);   // [row][ABSTRIDE]: (a,b) x 64 h
    #pragma unroll
    for (int mi = 0; mi < 4; mi++) {
        int r0 = wm * 64 + mi * 16 + (lane >> 2);
        #pragma unroll
        for (int nj = 0; nj < 4; nj++) {
            int h = wn * 16 + nj * 4 + (lane & 3);
            float wmv = sw512[2 * h], wsv = sw512[2 * h + 1];
            float2 v0 = { acc[mi][nj][0] + xv[2 * mi] * wmv,
                          acc[mi][nj][1] + xv[2 * mi] * wsv };
            float2 v1 = { acc[mi][nj][2] + xv[2 * mi + 1] * wmv,
                          acc[mi][nj][3] + xv[2 * mi + 1] * wsv };
            *(float2*)&AB[r0 * ABSTRIDE + 2 * h]       = v0;
            *(float2*)&AB[(r0 + 8) * ABSTRIDE + 2 * h] = v1;
        }
    }
    __syncthreads();

    // ---- fused MC epilogue: thread = (row, mc-half) ----
    const int row = tid >> 1;
    const int g   = tid & 1;

    ull e2[16];
    #pragma unroll
    for (int j = 0; j < 16; j++)
        e2[j] = ((const ull*)(sEps + g * 32))[j];

    ull acc2[16];
    #pragma unroll
    for (int j = 0; j < 16; j++) acc2[j] = 0ull;

    const float* abrow = &AB[row * ABSTRIDE];

    #pragma unroll 2
    for (int h2 = 0; h2 < 32; h2++) {            // two h per iteration
        float4 ab = *(const float4*)&abrow[4 * h2];      // a0,b0,a1,b1
        float2 ww = *(const float2*)&sW1[2 * h2];
        ull a0d = pk2(ab.x, ab.x), b0d = pk2(ab.y, ab.y);
        ull a1d = pk2(ab.z, ab.z), b1d = pk2(ab.w, ab.w);
        ull w0d = pk2(ww.x, ww.x), w1d = pk2(ww.y, ww.y);
        #pragma unroll
        for (int j = 0; j < 16; j++) {
            F2U t; t.u = fma2(e2[j], b0d, a0d);
            t.f.x = fmaxf(t.f.x, 0.0f); t.f.y = fmaxf(t.f.y, 0.0f);
            acc2[j] = fma2(t.u, w0d, acc2[j]);
            F2U s; s.u = fma2(e2[j], b1d, a1d);
            s.f.x = fmaxf(s.f.x, 0.0f); s.f.y = fmaxf(s.f.y, 0.0f);
            acc2[j] = fma2(s.u, w1d, acc2[j]);
        }
    }

    float* P = g_P + (size_t)blockIdx.x * (NROWS * N_MC)
             + (size_t)(rowBase + row) * N_MC + g * 32;
    #pragma unroll
    for (int q = 0; q < 8; q++) {
        F2U lo, hi; lo.u = acc2[2 * q]; hi.u = acc2[2 * q + 1];
        float4 o = { lo.f.x, lo.f.y, hi.f.x, hi.f.y };
        *(float4*)(P + 4 * q) = o;
    }
}

// -------- Kernel 3: reduce  pred = W1[0] + sum_cb P[cb]  (MLP 8) -------------
__global__ __launch_bounds__(256) void reduce_pred(const float* __restrict__ W1,
                                                   float* __restrict__ out_pred) {
    const int i0 = blockIdx.x * 256 + threadIdx.x;   // float4 index, +32768 stride
    const float4* P0 = (const float4*)g_P;
    const float4* P1 = (const float4*)(g_P + 1 * NROWS * N_MC);
    const float4* P2 = (const float4*)(g_P + 2 * NROWS * N_MC);
    const float4* P3 = (const float4*)(g_P + 3 * NROWS * N_MC);
    const float w0 = W1[0];
    float4* OP = (float4*)out_pred;
    #pragma unroll
    for (int k = 0; k < 2; k++) {
        int i = i0 + k * 32768;
        float4 a = P0[i], b = P1[i], c = P2[i], d = P3[i];
        float4 o;
        o.x = w0 + ((a.x + b.x) + (c.x + d.x));
        o.y = w0 + ((a.y + b.y) + (c.y + d.y));
        o.z = w0 + ((a.z + b.z) + (c.z + d.z));
        o.w = w0 + ((a.w + b.w) + (c.w + d.w));
        OP[i] = o;
    }
}

// ---------------------------------------------------------------------------
extern "C" void kernel_launch(void* const* d_in, const int* in_sizes, int n_in,
                              void* d_out, int out_size) {
    const float* params = (const float*)d_in[0];
    const float* W1     = (const float*)d_in[1];
    const float* x      = (const float*)d_in[2];
    const float* eps    = (const float*)d_in[3];

    float* out      = (float*)d_out;
    float* out_pred = out;
    float* out_m    = out + NROWS * N_MC;
    float* out_v    = out_m + LEN_M;

    cudaFuncSetAttribute(gemm_fused, cudaFuncAttributeMaxDynamicSharedMemorySize, GSMEM);

    prep_all<<<XBLK0 + NROWS / 2, 256>>>(params, x, out_m, out_v);
    gemm_fused<<<dim3(4, 32), 256, GSMEM>>>(W1, eps);
    reduce_pred<<<128, 256>>>(W1, out_pred);
}

// round 13
// speedup vs baseline: 1.0454x; 1.0454x over previous
#include <cuda_runtime.h>
#include <cuda_bf16.h>
#include <cstdint>

#define LEN_M   131328
#define D_H     256
#define N_MC    64
#define DDP1    513
#define NROWS   4096
#define NCOL    512        // interleaved: col 2h = A_h (m), 2h+1 = B_h (s)
#define KP      512        // MMA K (col 512 handled as rank-1 update)
#define NCHUNK  8          // 512 / 64
#define BKB     128        // bytes per smem row (64 bf16) = SW128 atom

// -------- persistent scratch (no allocs allowed) ---------------------------
__device__ __align__(128) __nv_bfloat16 g_xh[NROWS * KP];
__device__ __align__(128) __nv_bfloat16 g_xl[NROWS * KP];
__device__ __align__(128) __nv_bfloat16 g_bh[NCOL * KP];   // row 2h=m_h, 2h+1=s_h
__device__ __align__(128) __nv_bfloat16 g_bl[NCOL * KP];
__device__ __align__(128) float g_x512[NROWS];
__device__ __align__(128) float g_w512[NCOL];              // interleaved m/s
__device__ __align__(128) float g_P[4 * NROWS * N_MC];     // per-colblock partials

// -------- PTX helpers -------------------------------------------------------
__device__ __forceinline__ uint32_t s2u(const void* p) {
    uint32_t a;
    asm("{ .reg .u64 t; cvta.to.shared.u64 t, %1; cvt.u32.u64 %0, t; }"
        : "=r"(a) : "l"(p));
    return a;
}
#define SW128(o) ((o) ^ (((o) >> 3) & 0x70))

#define LDSM_X4(r, a)                                                         \
    asm volatile("ldmatrix.sync.aligned.m8n8.x4.shared.b16 {%0,%1,%2,%3}, [%4];" \
        : "=r"((r)[0]), "=r"((r)[1]), "=r"((r)[2]), "=r"((r)[3]) : "r"(a))

#define MMA16816(d, a, b)                                                     \
    asm volatile("mma.sync.aligned.m16n8k16.row.col.f32.bf16.bf16.f32 "       \
        "{%0,%1,%2,%3}, {%4,%5,%6,%7}, {%8,%9}, {%0,%1,%2,%3};"               \
        : "+f"((d)[0]), "+f"((d)[1]), "+f"((d)[2]), "+f"((d)[3])              \
        : "r"((a)[0]), "r"((a)[1]), "r"((a)[2]), "r"((a)[3]),                 \
          "r"((b)[0]), "r"((b)[1]))

__device__ __forceinline__ uint16_t bfbits(float f) {
    __nv_bfloat16 b = __float2bfloat16(f);
    return *(uint16_t*)&b;
}
__device__ __forceinline__ float bf2f(uint16_t u) {
    __nv_bfloat16 b = *(__nv_bfloat16*)&u;
    return __bfloat162float(b);
}

typedef unsigned long long ull;
union F2U { float2 f; ull u; };
__device__ __forceinline__ ull fma2(ull a, ull b, ull c) {
    ull r; asm("fma.rn.f32x2 %0, %1, %2, %3;" : "=l"(r) : "l"(a), "l"(b), "l"(c));
    return r;
}
__device__ __forceinline__ ull pk2(float x, float y) {
    ull r; asm("mov.b64 %0, {%1,%2};" : "=l"(r) : "f"(x), "f"(y)); return r;
}

// -------- Kernel 1: fused prep (ONE launch) ---------------------------------
// blocks 0..127 : weights d = 4b..4b+3 (smem transpose, 10KB smem)
// block  128    : weight row d = 512
// blocks 129..  : x rows (4 per block, 8 floats/thread, uint4 stores)
#define DCHUNK 4
#define XBLK0  129

__global__ __launch_bounds__(256) void prep_all(
        const float* __restrict__ params, const float* __restrict__ x,
        float* __restrict__ out_m, float* __restrict__ out_v) {
    const int b   = blockIdx.x;
    const int tid = threadIdx.x;

    if (b < 128) {
        __shared__ uint16_t tmh[256][DCHUNK + 1];
        __shared__ uint16_t tml[256][DCHUNK + 1];
        __shared__ uint16_t tsh[256][DCHUNK + 1];
        __shared__ uint16_t tsl[256][DCHUNK + 1];
        const int h = tid;
        #pragma unroll
        for (int j = 0; j < DCHUNK; j++) {
            int d = b * DCHUNK + j;
            int i = d * 256 + h;
            float m = params[i];                       // coalesced
            float v = fmaxf(params[LEN_M + i], 0.0f) + 1e-6f;
            float s = sqrtf(v);
            out_m[i] = m;
            out_v[i] = v;
            uint16_t mh = bfbits(m);
            uint16_t sh = bfbits(s);
            tmh[h][j] = mh;  tml[h][j] = bfbits(m - bf2f(mh));
            tsh[h][j] = sh;  tsl[h][j] = bfbits(s - bf2f(sh));
        }
        __syncthreads();
        const int colB = b * DCHUNK;
        auto pack = [&](uint16_t (*t)[DCHUNK + 1], int hh) -> uint2 {
            uint2 w;
            w.x = (uint32_t)t[hh][0] | ((uint32_t)t[hh][1] << 16);
            w.y = (uint32_t)t[hh][2] | ((uint32_t)t[hh][3] << 16);
            return w;
        };
        #pragma unroll
        for (int rr = 0; rr < 2; rr++) {               // rows tid, tid+256
            int r  = tid + rr * 256;
            int hh = r >> 1;
            uint2 wh = (r & 1) ? pack(tsh, hh) : pack(tmh, hh);
            uint2 wl = (r & 1) ? pack(tsl, hh) : pack(tml, hh);
            *(uint2*)(g_bh + (size_t)r * KP + colB) = wh;
            *(uint2*)(g_bl + (size_t)r * KP + colB) = wl;
        }
    } else if (b == 128) {
        const int h = tid;                              // d = 512 row
        int i = 512 * 256 + h;
        float m = params[i];
        float v = fmaxf(params[LEN_M + i], 0.0f) + 1e-6f;
        out_m[i] = m;
        out_v[i] = v;
        g_w512[2 * h]     = m;
        g_w512[2 * h + 1] = sqrtf(v);
    } else {
        // x: 4 rows per block, 64 threads/row, 8 floats/thread (MLP 8)
        const int r = tid >> 6;             // 0..3
        const int t = tid & 63;
        const int n = (b - XBLK0) * 4 + r;
        const size_t base = (size_t)n * DDP1 + 8 * t;
        float v[8];
        #pragma unroll
        for (int i = 0; i < 8; i++) v[i] = x[base + i];
        uint32_t hw[4], lw[4];
        #pragma unroll
        for (int i = 0; i < 4; i++) {
            uint16_t ha = bfbits(v[2 * i]), hb = bfbits(v[2 * i + 1]);
            hw[i] = (uint32_t)ha | ((uint32_t)hb << 16);
            lw[i] = (uint32_t)bfbits(v[2 * i] - bf2f(ha))
                  | ((uint32_t)bfbits(v[2 * i + 1] - bf2f(hb)) << 16);
        }
        ((uint4*)g_xh)[n * 64 + t] = make_uint4(hw[0], hw[1], hw[2], hw[3]);
        ((uint4*)g_xl)[n * 64 + t] = make_uint4(lw[0], lw[1], lw[2], lw[3]);
        if (t == 0) g_x512[n] = x[(size_t)n * DDP1 + 512];
    }
}

// -------- Kernel 2: HMMA GEMM + FUSED MC epilogue ---------------------------
// grid (4, 32): tile 128(M) x 128(N interleaved = 64 h). 8 warps 2(M)x4(N).
// 3-stage cp.async pipeline, chunk loop fully unrolled.
#define TILE_B   16384
#define CHSET_B  (4 * TILE_B)
#define NSTAGE   3
#define GSMEM    (1024 + NSTAGE * CHSET_B)
#define ABSTRIDE 132

__global__ __launch_bounds__(256, 1) void gemm_fused(const float* __restrict__ W1,
                                                     const float* __restrict__ eps) {
    extern __shared__ __align__(1024) char smem[];
    const uint32_t sb = s2u(smem);
    float* sw512 = (float*)smem;              // [0,512): 128 floats (interleaved)
    float* sW1   = (float*)(smem + 512);      // 64 floats W1[hBase+1 ..]
    float* sEps  = (float*)(smem + 768);      // 64 floats
    const uint32_t TB = sb + 1024;

    const int tid  = threadIdx.x;
    const int lane = tid & 31;
    const int warp = tid >> 5;
    const int wm = warp >> 2;                 // 0..1
    const int wn = warp & 3;                  // 0..3
    const int rowBase = blockIdx.y * 128;
    const int colBase = blockIdx.x * 128;
    const int hBase   = blockIdx.x * 64;

    if (tid < 128)                  sw512[tid]       = g_w512[colBase + tid];
    else if (tid < 192)             sW1[tid - 128]   = W1[hBase + (tid - 128) + 1];
    else                            sEps[tid - 192]  = eps[tid - 192];

    // hoisted epilogue operands: hide the g_x512 DRAM latency behind mainloop
    float xv[8];
    #pragma unroll
    for (int mi = 0; mi < 4; mi++) {
        int r = rowBase + wm * 64 + mi * 16 + (lane >> 2);
        xv[2 * mi]     = g_x512[r];
        xv[2 * mi + 1] = g_x512[r + 8];
    }

    float acc[4][4][4];
    #pragma unroll
    for (int mi = 0; mi < 4; mi++)
        #pragma unroll
        for (int nj = 0; nj < 4; nj++)
            #pragma unroll
            for (int q = 0; q < 4; q++)
                acc[mi][nj][q] = 0.0f;

    auto issue_chunk = [&](int c, int buf) {
        const uint32_t tb = TB + buf * CHSET_B;
        #pragma unroll
        for (int t = 0; t < 4; t++) {
            const char* gbase = (t == 0) ? (const char*)g_xh
                              : (t == 1) ? (const char*)g_xl
                              : (t == 2) ? (const char*)g_bh
                                         : (const char*)g_bl;
            const int rbase = (t < 2) ? rowBase : colBase;
            #pragma unroll
            for (int i = 0; i < 4; i++) {
                int q = tid + i * 256;
                int r = q >> 3, s = q & 7;
                const char* gp = gbase + (size_t)(rbase + r) * (KP * 2)
                               + c * BKB + s * 16;
                uint32_t sp = tb + t * TILE_B + SW128(r * BKB + s * 16);
                asm volatile("cp.async.cg.shared.global [%0], [%1], 16;"
                             :: "r"(sp), "l"(gp));
            }
        }
        asm volatile("cp.async.commit_group;" ::: "memory");
    };

    issue_chunk(0, 0);
    issue_chunk(1, 1);

    #pragma unroll
    for (int c = 0; c < NCHUNK; c++) {
        const int buf = c % NSTAGE;           // constant after unroll

        if (c < NCHUNK - 1) {
            asm volatile("cp.async.wait_group 1;" ::: "memory");
        } else {
            asm volatile("cp.async.wait_group 0;" ::: "memory");
        }
        __syncthreads();
        if (c + 2 < NCHUNK)
            issue_chunk(c + 2, (c + 2) % NSTAGE);

        const uint32_t Ah = TB + buf * CHSET_B;
        const uint32_t Al = Ah + TILE_B;
        const uint32_t Bh = Al + TILE_B;
        const uint32_t Bl = Bh + TILE_B;

        #pragma unroll
        for (int s = 0; s < 4; s++) {
            const int k0 = s * 16;
            uint32_t ah[4][4], al[4][4], bhf[4][2], blf[4][2];

            #pragma unroll
            for (int mi = 0; mi < 4; mi++) {
                int row = wm * 64 + mi * 16 + (lane & 15);
                int col = k0 + ((lane >> 4) << 3);
                uint32_t off = SW128(row * BKB + col * 2);
                LDSM_X4(ah[mi], Ah + off);
                LDSM_X4(al[mi], Al + off);
            }
            #pragma unroll
            for (int p = 0; p < 2; p++) {
                int row = wn * 32 + p * 16 + (lane & 7) + ((lane & 16) >> 1);
                int col = k0 + (lane & 8);
                uint32_t off = SW128(row * BKB + col * 2);
                uint32_t r[4];
                LDSM_X4(r, Bh + off);
                bhf[p * 2][0] = r[0]; bhf[p * 2][1] = r[1];
                bhf[p * 2 + 1][0] = r[2]; bhf[p * 2 + 1][1] = r[3];
                LDSM_X4(r, Bl + off);
                blf[p * 2][0] = r[0]; blf[p * 2][1] = r[1];
                blf[p * 2 + 1][0] = r[2]; blf[p * 2 + 1][1] = r[3];
            }

            #pragma unroll
            for (int mi = 0; mi < 4; mi++)
                #pragma unroll
                for (int nj = 0; nj < 4; nj++) {
                    MMA16816(acc[mi][nj], ah[mi], bhf[nj]);
                    MMA16816(acc[mi][nj], ah[mi], blf[nj]);
                    MMA16816(acc[mi][nj], al[mi], bhf[nj]);
                }
        }
    }

    // ---- stage (a,b) pairs into smem (reuse pipeline region) ----
    __syncthreads();                     // all MMA smem reads done

    float* AB = (float*)(smem + 1024);   // [row][ABSTRIDE]: (a,b) x 64 h
    #pragma unroll
    for (int mi = 0; mi < 4; mi++) {
        int r0 = wm * 64 + mi * 16 + (lane >> 2);
        #pragma unroll
        for (int nj = 0; nj < 4; nj++) {
            int h = wn * 16 + nj * 4 + (lane & 3);
            float wmv = sw512[2 * h], wsv = sw512[2 * h + 1];
            float2 v0 = { acc[mi][nj][0] + xv[2 * mi] * wmv,
                          acc[mi][nj][1] + xv[2 * mi] * wsv };
            float2 v1 = { acc[mi][nj][2] + xv[2 * mi + 1] * wmv,
                          acc[mi][nj][3] + xv[2 * mi + 1] * wsv };
            *(float2*)&AB[r0 * ABSTRIDE + 2 * h]       = v0;
            *(float2*)&AB[(r0 + 8) * ABSTRIDE + 2 * h] = v1;
        }
    }
    __syncthreads();

    // ---- fused MC epilogue: thread = (row, mc-half) ----
    const int row = tid >> 1;
    const int g   = tid & 1;

    ull e2[16];
    #pragma unroll
    for (int j = 0; j < 16; j++)
        e2[j] = ((const ull*)(sEps + g * 32))[j];

    ull acc2[16];
    #pragma unroll
    for (int j = 0; j < 16; j++) acc2[j] = 0ull;

    const float* abrow = &AB[row * ABSTRIDE];

    #pragma unroll 2
    for (int h2 = 0; h2 < 32; h2++) {            // two h per iteration
        float4 ab = *(const float4*)&abrow[4 * h2];      // a0,b0,a1,b1
        float2 ww = *(const float2*)&sW1[2 * h2];
        ull a0d = pk2(ab.x, ab.x), b0d = pk2(ab.y, ab.y);
        ull a1d = pk2(ab.z, ab.z), b1d = pk2(ab.w, ab.w);
        ull w0d = pk2(ww.x, ww.x), w1d = pk2(ww.y, ww.y);
        #pragma unroll
        for (int j = 0; j < 16; j++) {
            F2U t; t.u = fma2(e2[j], b0d, a0d);
            t.f.x = fmaxf(t.f.x, 0.0f); t.f.y = fmaxf(t.f.y, 0.0f);
            acc2[j] = fma2(t.u, w0d, acc2[j]);
            F2U s; s.u = fma2(e2[j], b1d, a1d);
            s.f.x = fmaxf(s.f.x, 0.0f); s.f.y = fmaxf(s.f.y, 0.0f);
            acc2[j] = fma2(s.u, w1d, acc2[j]);
        }
    }

    float* P = g_P + (size_t)blockIdx.x * (NROWS * N_MC)
             + (size_t)(rowBase + row) * N_MC + g * 32;
    #pragma unroll
    for (int q = 0; q < 8; q++) {
        F2U lo, hi; lo.u = acc2[2 * q]; hi.u = acc2[2 * q + 1];
        float4 o = { lo.f.x, lo.f.y, hi.f.x, hi.f.y };
        *(float4*)(P + 4 * q) = o;
    }
}

// -------- Kernel 3: reduce  pred = W1[0] + sum_cb P[cb]  (MLP 8) -------------
__global__ __launch_bounds__(256) void reduce_pred(const float* __restrict__ W1,
                                                   float* __restrict__ out_pred) {
    const int i0 = blockIdx.x * 256 + threadIdx.x;   // float4 index, +32768 stride
    const float4* P0 = (const float4*)g_P;
    const float4* P1 = (const float4*)(g_P + 1 * NROWS * N_MC);
    const float4* P2 = (const float4*)(g_P + 2 * NROWS * N_MC);
    const float4* P3 = (const float4*)(g_P + 3 * NROWS * N_MC);
    const float w0 = W1[0];
    float4* OP = (float4*)out_pred;
    #pragma unroll
    for (int k = 0; k < 2; k++) {
        int i = i0 + k * 32768;
        float4 a = P0[i], b = P1[i], c = P2[i], d = P3[i];
        float4 o;
        o.x = w0 + ((a.x + b.x) + (c.x + d.x));
        o.y = w0 + ((a.y + b.y) + (c.y + d.y));
        o.z = w0 + ((a.z + b.z) + (c.z + d.z));
        o.w = w0 + ((a.w + b.w) + (c.w + d.w));
        OP[i] = o;
    }
}

// ---------------------------------------------------------------------------
extern "C" void kernel_launch(void* const* d_in, const int* in_sizes, int n_in,
                              void* d_out, int out_size) {
    const float* params = (const float*)d_in[0];
    const float* W1     = (const float*)d_in[1];
    const float* x      = (const float*)d_in[2];
    const float* eps    = (const float*)d_in[3];

    float* out      = (float*)d_out;
    float* out_pred = out;
    float* out_m    = out + NROWS * N_MC;
    float* out_v    = out_m + LEN_M;

    cudaFuncSetAttribute(gemm_fused, cudaFuncAttributeMaxDynamicSharedMemorySize, GSMEM);

    prep_all<<<XBLK0 + NROWS / 4, 256>>>(params, x, out_m, out_v);
    gemm_fused<<<dim3(4, 32), 256, GSMEM>>>(W1, eps);
    reduce_pred<<<128, 256>>>(W1, out_pred);
}

// round 14
// speedup vs baseline: 1.0643x; 1.0181x over previous
#include <cuda_runtime.h>
#include <cuda_bf16.h>
#include <cstdint>

#define LEN_M   131328
#define D_H     256
#define N_MC    64
#define DDP1    513
#define NROWS   4096
#define NCOL    512        // interleaved: col 2h = A_h (m), 2h+1 = B_h (s)
#define KP      512        // MMA K (col 512 handled as rank-1 update)
#define NCHUNK  8          // 512 / 64
#define BKB     128        // bytes per smem row (64 bf16) = SW128 atom

// -------- persistent scratch (no allocs allowed) ---------------------------
__device__ __align__(128) __nv_bfloat16 g_xh[NROWS * KP];
__device__ __align__(128) __nv_bfloat16 g_xl[NROWS * KP];
__device__ __align__(128) __nv_bfloat16 g_bh[NCOL * KP];   // row 2h=m_h, 2h+1=s_h
__device__ __align__(128) __nv_bfloat16 g_bl[NCOL * KP];
__device__ __align__(128) float g_x512[NROWS];
__device__ __align__(128) float g_w512[NCOL];              // interleaved m/s

// -------- PTX helpers -------------------------------------------------------
__device__ __forceinline__ uint32_t s2u(const void* p) {
    uint32_t a;
    asm("{ .reg .u64 t; cvta.to.shared.u64 t, %1; cvt.u32.u64 %0, t; }"
        : "=r"(a) : "l"(p));
    return a;
}
#define SW128(o) ((o) ^ (((o) >> 3) & 0x70))

#define LDSM_X4(r, a)                                                         \
    asm volatile("ldmatrix.sync.aligned.m8n8.x4.shared.b16 {%0,%1,%2,%3}, [%4];" \
        : "=r"((r)[0]), "=r"((r)[1]), "=r"((r)[2]), "=r"((r)[3]) : "r"(a))

#define MMA16816(d, a, b)                                                     \
    asm volatile("mma.sync.aligned.m16n8k16.row.col.f32.bf16.bf16.f32 "       \
        "{%0,%1,%2,%3}, {%4,%5,%6,%7}, {%8,%9}, {%0,%1,%2,%3};"               \
        : "+f"((d)[0]), "+f"((d)[1]), "+f"((d)[2]), "+f"((d)[3])              \
        : "r"((a)[0]), "r"((a)[1]), "r"((a)[2]), "r"((a)[3]),                 \
          "r"((b)[0]), "r"((b)[1]))

__device__ __forceinline__ uint16_t bfbits(float f) {
    __nv_bfloat16 b = __float2bfloat16(f);
    return *(uint16_t*)&b;
}
__device__ __forceinline__ float bf2f(uint16_t u) {
    __nv_bfloat16 b = *(__nv_bfloat16*)&u;
    return __bfloat162float(b);
}

typedef unsigned long long ull;
union F2U { float2 f; ull u; };
__device__ __forceinline__ ull fma2(ull a, ull b, ull c) {
    ull r; asm("fma.rn.f32x2 %0, %1, %2, %3;" : "=l"(r) : "l"(a), "l"(b), "l"(c));
    return r;
}
__device__ __forceinline__ ull pk2(float x, float y) {
    ull r; asm("mov.b64 %0, {%1,%2};" : "=l"(r) : "f"(x), "f"(y)); return r;
}

// DSMEM read: float4 from the same smem offset in cluster CTA `rank`
__device__ __forceinline__ float4 dsmem_ld4(uint32_t saddr, uint32_t rank) {
    uint32_t ra;
    asm volatile("mapa.shared::cluster.u32 %0, %1, %2;"
                 : "=r"(ra) : "r"(saddr), "r"(rank));
    float4 v;
    asm volatile("ld.shared::cluster.v4.f32 {%0,%1,%2,%3}, [%4];"
                 : "=f"(v.x), "=f"(v.y), "=f"(v.z), "=f"(v.w) : "r"(ra));
    return v;
}
#define CLUSTER_ARRIVE() asm volatile("barrier.cluster.arrive.aligned;" ::: "memory")
#define CLUSTER_WAIT()   asm volatile("barrier.cluster.wait.aligned;" ::: "memory")

// -------- Kernel 1: fused prep (ONE launch) ---------------------------------
// blocks 0..127 : weights d = 4b..4b+3 (smem transpose, 10KB smem)
// block  128    : weight row d = 512
// blocks 129..  : x rows (4 per block, 8 floats/thread, uint4 stores)
#define DCHUNK 4
#define XBLK0  129

__global__ __launch_bounds__(256) void prep_all(
        const float* __restrict__ params, const float* __restrict__ x,
        float* __restrict__ out_m, float* __restrict__ out_v) {
    const int b   = blockIdx.x;
    const int tid = threadIdx.x;

    if (b < 128) {
        __shared__ uint16_t tmh[256][DCHUNK + 1];
        __shared__ uint16_t tml[256][DCHUNK + 1];
        __shared__ uint16_t tsh[256][DCHUNK + 1];
        __shared__ uint16_t tsl[256][DCHUNK + 1];
        const int h = tid;
        #pragma unroll
        for (int j = 0; j < DCHUNK; j++) {
            int d = b * DCHUNK + j;
            int i = d * 256 + h;
            float m = params[i];                       // coalesced
            float v = fmaxf(params[LEN_M + i], 0.0f) + 1e-6f;
            float s = sqrtf(v);
            out_m[i] = m;
            out_v[i] = v;
            uint16_t mh = bfbits(m);
            uint16_t sh = bfbits(s);
            tmh[h][j] = mh;  tml[h][j] = bfbits(m - bf2f(mh));
            tsh[h][j] = sh;  tsl[h][j] = bfbits(s - bf2f(sh));
        }
        __syncthreads();
        const int colB = b * DCHUNK;
        auto pack = [&](uint16_t (*t)[DCHUNK + 1], int hh) -> uint2 {
            uint2 w;
            w.x = (uint32_t)t[hh][0] | ((uint32_t)t[hh][1] << 16);
            w.y = (uint32_t)t[hh][2] | ((uint32_t)t[hh][3] << 16);
            return w;
        };
        #pragma unroll
        for (int rr = 0; rr < 2; rr++) {               // rows tid, tid+256
            int r  = tid + rr * 256;
            int hh = r >> 1;
            uint2 wh = (r & 1) ? pack(tsh, hh) : pack(tmh, hh);
            uint2 wl = (r & 1) ? pack(tsl, hh) : pack(tml, hh);
            *(uint2*)(g_bh + (size_t)r * KP + colB) = wh;
            *(uint2*)(g_bl + (size_t)r * KP + colB) = wl;
        }
    } else if (b == 128) {
        const int h = tid;                              // d = 512 row
        int i = 512 * 256 + h;
        float m = params[i];
        float v = fmaxf(params[LEN_M + i], 0.0f) + 1e-6f;
        out_m[i] = m;
        out_v[i] = v;
        g_w512[2 * h]     = m;
        g_w512[2 * h + 1] = sqrtf(v);
    } else {
        // x: 4 rows per block, 64 threads/row, 8 floats/thread (MLP 8)
        const int r = tid >> 6;             // 0..3
        const int t = tid & 63;
        const int n = (b - XBLK0) * 4 + r;
        const size_t base = (size_t)n * DDP1 + 8 * t;
        float v[8];
        #pragma unroll
        for (int i = 0; i < 8; i++) v[i] = x[base + i];
        uint32_t hw[4], lw[4];
        #pragma unroll
        for (int i = 0; i < 4; i++) {
            uint16_t ha = bfbits(v[2 * i]), hb = bfbits(v[2 * i + 1]);
            hw[i] = (uint32_t)ha | ((uint32_t)hb << 16);
            lw[i] = (uint32_t)bfbits(v[2 * i] - bf2f(ha))
                  | ((uint32_t)bfbits(v[2 * i + 1] - bf2f(hb)) << 16);
        }
        ((uint4*)g_xh)[n * 64 + t] = make_uint4(hw[0], hw[1], hw[2], hw[3]);
        ((uint4*)g_xl)[n * 64 + t] = make_uint4(lw[0], lw[1], lw[2], lw[3]);
        if (t == 0) g_x512[n] = x[(size_t)n * DDP1 + 512];
    }
}

// -------- Kernel 2: HMMA GEMM + FUSED MC epilogue + DSMEM cluster reduce ----
// grid (4, 32), cluster (4,1,1): the 4 column-CTAs of one row-block form a
// cluster. Partials stay in smem; rank r reduces rows [32r,32r+32) over all
// 4 peers via mapa/ld.shared::cluster (fixed order -> deterministic) and
// writes out_pred directly. No g_P, no reduce kernel.
#define TILE_B   16384
#define CHSET_B  (4 * TILE_B)
#define NSTAGE   3
#define GSMEM    (1024 + NSTAGE * CHSET_B)
#define ABSTRIDE 132
#define PB_OFF   (1024 + 128 * ABSTRIDE * 4)      // 68608; P: 32KB, fits GSMEM

__global__ __launch_bounds__(256, 1) __cluster_dims__(4, 1, 1)
void gemm_fused(const float* __restrict__ W1,
                const float* __restrict__ eps,
                float* __restrict__ out_pred) {
    extern __shared__ __align__(1024) char smem[];
    const uint32_t sb = s2u(smem);
    float* sw512 = (float*)smem;              // [0,512): 128 floats (interleaved)
    float* sW1   = (float*)(smem + 512);      // 64 floats W1[hBase+1 ..]
    float* sEps  = (float*)(smem + 768);      // 64 floats
    const uint32_t TB = sb + 1024;

    const int tid  = threadIdx.x;
    const int lane = tid & 31;
    const int warp = tid >> 5;
    const int wm = warp >> 2;                 // 0..1
    const int wn = warp & 3;                  // 0..3
    const int rowBase = blockIdx.y * 128;
    const int colBase = blockIdx.x * 128;
    const int hBase   = blockIdx.x * 64;

    if (tid < 128)                  sw512[tid]       = g_w512[colBase + tid];
    else if (tid < 192)             sW1[tid - 128]   = W1[hBase + (tid - 128) + 1];
    else                            sEps[tid - 192]  = eps[tid - 192];

    // hoisted epilogue operands: hide the g_x512 DRAM latency behind mainloop
    float xv[8];
    #pragma unroll
    for (int mi = 0; mi < 4; mi++) {
        int r = rowBase + wm * 64 + mi * 16 + (lane >> 2);
        xv[2 * mi]     = g_x512[r];
        xv[2 * mi + 1] = g_x512[r + 8];
    }

    float acc[4][4][4];
    #pragma unroll
    for (int mi = 0; mi < 4; mi++)
        #pragma unroll
        for (int nj = 0; nj < 4; nj++)
            #pragma unroll
            for (int q = 0; q < 4; q++)
                acc[mi][nj][q] = 0.0f;

    auto issue_chunk = [&](int c, int buf) {
        const uint32_t tb = TB + buf * CHSET_B;
        #pragma unroll
        for (int t = 0; t < 4; t++) {
            const char* gbase = (t == 0) ? (const char*)g_xh
                              : (t == 1) ? (const char*)g_xl
                              : (t == 2) ? (const char*)g_bh
                                         : (const char*)g_bl;
            const int rbase = (t < 2) ? rowBase : colBase;
            #pragma unroll
            for (int i = 0; i < 4; i++) {
                int q = tid + i * 256;
                int r = q >> 3, s = q & 7;
                const char* gp = gbase + (size_t)(rbase + r) * (KP * 2)
                               + c * BKB + s * 16;
                uint32_t sp = tb + t * TILE_B + SW128(r * BKB + s * 16);
                asm volatile("cp.async.cg.shared.global [%0], [%1], 16;"
                             :: "r"(sp), "l"(gp));
            }
        }
        asm volatile("cp.async.commit_group;" ::: "memory");
    };

    issue_chunk(0, 0);
    issue_chunk(1, 1);

    #pragma unroll
    for (int c = 0; c < NCHUNK; c++) {
        const int buf = c % NSTAGE;           // constant after unroll

        if (c < NCHUNK - 1) {
            asm volatile("cp.async.wait_group 1;" ::: "memory");
        } else {
            asm volatile("cp.async.wait_group 0;" ::: "memory");
        }
        __syncthreads();
        if (c + 2 < NCHUNK)
            issue_chunk(c + 2, (c + 2) % NSTAGE);

        const uint32_t Ah = TB + buf * CHSET_B;
        const uint32_t Al = Ah + TILE_B;
        const uint32_t Bh = Al + TILE_B;
        const uint32_t Bl = Bh + TILE_B;

        #pragma unroll
        for (int s = 0; s < 4; s++) {
            const int k0 = s * 16;
            uint32_t ah[4][4], al[4][4], bhf[4][2], blf[4][2];

            #pragma unroll
            for (int mi = 0; mi < 4; mi++) {
                int row = wm * 64 + mi * 16 + (lane & 15);
                int col = k0 + ((lane >> 4) << 3);
                uint32_t off = SW128(row * BKB + col * 2);
                LDSM_X4(ah[mi], Ah + off);
                LDSM_X4(al[mi], Al + off);
            }
            #pragma unroll
            for (int p = 0; p < 2; p++) {
                int row = wn * 32 + p * 16 + (lane & 7) + ((lane & 16) >> 1);
                int col = k0 + (lane & 8);
                uint32_t off = SW128(row * BKB + col * 2);
                uint32_t r[4];
                LDSM_X4(r, Bh + off);
                bhf[p * 2][0] = r[0]; bhf[p * 2][1] = r[1];
                bhf[p * 2 + 1][0] = r[2]; bhf[p * 2 + 1][1] = r[3];
                LDSM_X4(r, Bl + off);
                blf[p * 2][0] = r[0]; blf[p * 2][1] = r[1];
                blf[p * 2 + 1][0] = r[2]; blf[p * 2 + 1][1] = r[3];
            }

            #pragma unroll
            for (int mi = 0; mi < 4; mi++)
                #pragma unroll
                for (int nj = 0; nj < 4; nj++) {
                    MMA16816(acc[mi][nj], ah[mi], bhf[nj]);
                    MMA16816(acc[mi][nj], ah[mi], blf[nj]);
                    MMA16816(acc[mi][nj], al[mi], bhf[nj]);
                }
        }
    }

    // ---- stage (a,b) pairs into smem (reuse pipeline region) ----
    __syncthreads();                     // all MMA smem reads done

    float* AB = (float*)(smem + 1024);   // [row][ABSTRIDE]: (a,b) x 64 h
    #pragma unroll
    for (int mi = 0; mi < 4; mi++) {
        int r0 = wm * 64 + mi * 16 + (lane >> 2);
        #pragma unroll
        for (int nj = 0; nj < 4; nj++) {
            int h = wn * 16 + nj * 4 + (lane & 3);
            float wmv = sw512[2 * h], wsv = sw512[2 * h + 1];
            float2 v0 = { acc[mi][nj][0] + xv[2 * mi] * wmv,
                          acc[mi][nj][1] + xv[2 * mi] * wsv };
            float2 v1 = { acc[mi][nj][2] + xv[2 * mi + 1] * wmv,
                          acc[mi][nj][3] + xv[2 * mi + 1] * wsv };
            *(float2*)&AB[r0 * ABSTRIDE + 2 * h]       = v0;
            *(float2*)&AB[(r0 + 8) * ABSTRIDE + 2 * h] = v1;
        }
    }
    __syncthreads();

    // ---- fused MC epilogue: thread = (row, mc-half) ----
    const int row = tid >> 1;
    const int g   = tid & 1;

    ull e2[16];
    #pragma unroll
    for (int j = 0; j < 16; j++)
        e2[j] = ((const ull*)(sEps + g * 32))[j];

    ull acc2[16];
    #pragma unroll
    for (int j = 0; j < 16; j++) acc2[j] = 0ull;

    const float* abrow = &AB[row * ABSTRIDE];

    #pragma unroll 2
    for (int h2 = 0; h2 < 32; h2++) {            // two h per iteration
        float4 ab = *(const float4*)&abrow[4 * h2];      // a0,b0,a1,b1
        float2 ww = *(const float2*)&sW1[2 * h2];
        ull a0d = pk2(ab.x, ab.x), b0d = pk2(ab.y, ab.y);
        ull a1d = pk2(ab.z, ab.z), b1d = pk2(ab.w, ab.w);
        ull w0d = pk2(ww.x, ww.x), w1d = pk2(ww.y, ww.y);
        #pragma unroll
        for (int j = 0; j < 16; j++) {
            F2U t; t.u = fma2(e2[j], b0d, a0d);
            t.f.x = fmaxf(t.f.x, 0.0f); t.f.y = fmaxf(t.f.y, 0.0f);
            acc2[j] = fma2(t.u, w0d, acc2[j]);
            F2U s; s.u = fma2(e2[j], b1d, a1d);
            s.f.x = fmaxf(s.f.x, 0.0f); s.f.y = fmaxf(s.f.y, 0.0f);
            acc2[j] = fma2(s.u, w1d, acc2[j]);
        }
    }

    // partial -> SMEM (this CTA's h-quarter contribution, 128 rows x 64 mc)
    float* P = (float*)(smem + PB_OFF) + row * N_MC + g * 32;
    #pragma unroll
    for (int q = 0; q < 8; q++) {
        F2U lo, hi; lo.u = acc2[2 * q]; hi.u = acc2[2 * q + 1];
        float4 o = { lo.f.x, lo.f.y, hi.f.x, hi.f.y };
        *(float4*)(P + 4 * q) = o;
    }

    // ---- cluster DSMEM reduce: rank r outputs rows [32r, 32r+32) ----------
    CLUSTER_ARRIVE();                    // release: my P writes visible
    CLUSTER_WAIT();                      // acquire: all peers' P visible

    const uint32_t rank = blockIdx.x;    // cluster spans x: rank == bx
    const uint32_t sP   = sb + PB_OFF;
    const float w0 = W1[0];
    float4* OP = (float4*)out_pred;
    #pragma unroll
    for (int k = 0; k < 2; k++) {
        int p4 = rank * 512 + tid + k * 256;       // float4 idx in P
        uint32_t addr = sP + p4 * 16;
        float4 a = dsmem_ld4(addr, 0);
        float4 b = dsmem_ld4(addr, 1);
        float4 c = dsmem_ld4(addr, 2);
        float4 d = dsmem_ld4(addr, 3);
        float4 o;                                  // same order as old reduce
        o.x = w0 + ((a.x + b.x) + (c.x + d.x));
        o.y = w0 + ((a.y + b.y) + (c.y + d.y));
        o.z = w0 + ((a.z + b.z) + (c.z + d.z));
        o.w = w0 + ((a.w + b.w) + (c.w + d.w));
        OP[rowBase * 16 + p4] = o;                 // (rowBase+row)*16 + col
    }

    CLUSTER_ARRIVE();                    // keep peer smem alive until all read
    CLUSTER_WAIT();
}

// ---------------------------------------------------------------------------
extern "C" void kernel_launch(void* const* d_in, const int* in_sizes, int n_in,
                              void* d_out, int out_size) {
    const float* params = (const float*)d_in[0];
    const float* W1     = (const float*)d_in[1];
    const float* x      = (const float*)d_in[2];
    const float* eps    = (const float*)d_in[3];

    float* out      = (float*)d_out;
    float* out_pred = out;
    float* out_m    = out + NROWS * N_MC;
    float* out_v    = out_m + LEN_M;

    cudaFuncSetAttribute(gemm_fused, cudaFuncAttributeMaxDynamicSharedMemorySize, GSMEM);

    prep_all<<<XBLK0 + NROWS / 4, 256>>>(params, x, out_m, out_v);
    gemm_fused<<<dim3(4, 32), 256, GSMEM>>>(W1, eps, out_pred);
}

// round 15
// speedup vs baseline: 1.5006x; 1.4100x over previous
#include <cuda_runtime.h>
#include <cuda_fp16.h>
#include <cstdint>

#define LEN_M   131328
#define D_H     256
#define N_MC    64
#define DDP1    513
#define NROWS   4096
#define NCOL    512        // interleaved: col 2h = A_h (m), 2h+1 = B_h (s)
#define KP      512        // MMA K (col 512 handled as rank-1 update)
#define NCHUNK  8          // 512 / 64
#define BKB     128        // bytes per smem row (64 fp16) = SW128 atom

// -------- persistent scratch (no allocs allowed) ---------------------------
__device__ __align__(128) __half g_x16[NROWS * KP];        // x in fp16
__device__ __align__(128) __half g_b16[NCOL * KP];         // row 2h=m_h, 2h+1=s_h
__device__ __align__(128) float g_x512[NROWS];
__device__ __align__(128) float g_w512[NCOL];              // interleaved m/s

// -------- PTX helpers -------------------------------------------------------
__device__ __forceinline__ uint32_t s2u(const void* p) {
    uint32_t a;
    asm("{ .reg .u64 t; cvta.to.shared.u64 t, %1; cvt.u32.u64 %0, t; }"
        : "=r"(a) : "l"(p));
    return a;
}
#define SW128(o) ((o) ^ (((o) >> 3) & 0x70))

#define LDSM_X4(r, a)                                                         \
    asm volatile("ldmatrix.sync.aligned.m8n8.x4.shared.b16 {%0,%1,%2,%3}, [%4];" \
        : "=r"((r)[0]), "=r"((r)[1]), "=r"((r)[2]), "=r"((r)[3]) : "r"(a))

#define MMA16816F16(d, a, b)                                                  \
    asm volatile("mma.sync.aligned.m16n8k16.row.col.f32.f16.f16.f32 "         \
        "{%0,%1,%2,%3}, {%4,%5,%6,%7}, {%8,%9}, {%0,%1,%2,%3};"               \
        : "+f"((d)[0]), "+f"((d)[1]), "+f"((d)[2]), "+f"((d)[3])              \
        : "r"((a)[0]), "r"((a)[1]), "r"((a)[2]), "r"((a)[3]),                 \
          "r"((b)[0]), "r"((b)[1]))

__device__ __forceinline__ uint16_t hfbits(float f) {
    __half h = __float2half_rn(f);
    return *(uint16_t*)&h;
}

typedef unsigned long long ull;
union F2U { float2 f; ull u; };
__device__ __forceinline__ ull fma2(ull a, ull b, ull c) {
    ull r; asm("fma.rn.f32x2 %0, %1, %2, %3;" : "=l"(r) : "l"(a), "l"(b), "l"(c));
    return r;
}
__device__ __forceinline__ ull pk2(float x, float y) {
    ull r; asm("mov.b64 %0, {%1,%2};" : "=l"(r) : "f"(x), "f"(y)); return r;
}

// DSMEM read: float4 from the same smem offset in cluster CTA `rank`
__device__ __forceinline__ float4 dsmem_ld4(uint32_t saddr, uint32_t rank) {
    uint32_t ra;
    asm volatile("mapa.shared::cluster.u32 %0, %1, %2;"
                 : "=r"(ra) : "r"(saddr), "r"(rank));
    float4 v;
    asm volatile("ld.shared::cluster.v4.f32 {%0,%1,%2,%3}, [%4];"
                 : "=f"(v.x), "=f"(v.y), "=f"(v.z), "=f"(v.w) : "r"(ra));
    return v;
}
#define CLUSTER_ARRIVE() asm volatile("barrier.cluster.arrive.aligned;" ::: "memory")
#define CLUSTER_WAIT()   asm volatile("barrier.cluster.wait.aligned;" ::: "memory")

// -------- Kernel 1: fused prep (ONE launch) ---------------------------------
// blocks 0..127 : weights d = 4b..4b+3 (smem transpose, 5KB smem)
// block  128    : weight row d = 512
// blocks 129..  : x rows (4 per block, 8 floats/thread, one uint4 store)
#define DCHUNK 4
#define XBLK0  129

__global__ __launch_bounds__(256) void prep_all(
        const float* __restrict__ params, const float* __restrict__ x,
        float* __restrict__ out_m, float* __restrict__ out_v) {
    const int b   = blockIdx.x;
    const int tid = threadIdx.x;

    if (b < 128) {
        __shared__ uint16_t tmh[256][DCHUNK + 1];
        __shared__ uint16_t tsh[256][DCHUNK + 1];
        const int h = tid;
        #pragma unroll
        for (int j = 0; j < DCHUNK; j++) {
            int d = b * DCHUNK + j;
            int i = d * 256 + h;
            float m = params[i];                       // coalesced
            float v = fmaxf(params[LEN_M + i], 0.0f) + 1e-6f;
            float s = sqrtf(v);
            out_m[i] = m;
            out_v[i] = v;
            tmh[h][j] = hfbits(m);
            tsh[h][j] = hfbits(s);
        }
        __syncthreads();
        const int colB = b * DCHUNK;
        auto pack = [&](uint16_t (*t)[DCHUNK + 1], int hh) -> uint2 {
            uint2 w;
            w.x = (uint32_t)t[hh][0] | ((uint32_t)t[hh][1] << 16);
            w.y = (uint32_t)t[hh][2] | ((uint32_t)t[hh][3] << 16);
            return w;
        };
        #pragma unroll
        for (int rr = 0; rr < 2; rr++) {               // rows tid, tid+256
            int r  = tid + rr * 256;
            int hh = r >> 1;
            uint2 w = (r & 1) ? pack(tsh, hh) : pack(tmh, hh);
            *(uint2*)(g_b16 + (size_t)r * KP + colB) = w;
        }
    } else if (b == 128) {
        const int h = tid;                              // d = 512 row
        int i = 512 * 256 + h;
        float m = params[i];
        float v = fmaxf(params[LEN_M + i], 0.0f) + 1e-6f;
        out_m[i] = m;
        out_v[i] = v;
        g_w512[2 * h]     = m;
        g_w512[2 * h + 1] = sqrtf(v);
    } else {
        // x: 4 rows per block, 64 threads/row, 8 floats/thread -> one uint4
        const int r = tid >> 6;             // 0..3
        const int t = tid & 63;
        const int n = (b - XBLK0) * 4 + r;
        const size_t base = (size_t)n * DDP1 + 8 * t;
        float v[8];
        #pragma unroll
        for (int i = 0; i < 8; i++) v[i] = x[base + i];
        uint32_t hw[4];
        #pragma unroll
        for (int i = 0; i < 4; i++)
            hw[i] = (uint32_t)hfbits(v[2 * i]) | ((uint32_t)hfbits(v[2 * i + 1]) << 16);
        ((uint4*)g_x16)[n * 64 + t] = make_uint4(hw[0], hw[1], hw[2], hw[3]);
        if (t == 0) g_x512[n] = x[(size_t)n * DDP1 + 512];
    }
}

// -------- Kernel 2: fp16 HMMA GEMM + FUSED MC epilogue + DSMEM reduce -------
// grid (4, 32), cluster (4,1,1). Tile 128(M) x 128(N interleaved = 64 h).
// 8 warps 2(M)x4(N). SINGLE fp16 pass (fp32 accum). 3-stage cp.async pipeline.
#define TILE_B   16384                  // 128 rows x 128B (64 fp16)
#define CHSET_B  (2 * TILE_B)           // A | B = 32KB
#define NSTAGE   3
#define ABSTRIDE 132
#define PB_OFF   (1024 + 128 * ABSTRIDE * 4)      // 68608
#define GSMEM    (PB_OFF + 128 * N_MC * 4)        // 101376 (> 1024+3*32KB)

__global__ __launch_bounds__(256, 1) __cluster_dims__(4, 1, 1)
void gemm_fused(const float* __restrict__ W1,
                const float* __restrict__ eps,
                float* __restrict__ out_pred) {
    extern __shared__ __align__(1024) char smem[];
    const uint32_t sb = s2u(smem);
    float* sw512 = (float*)smem;              // [0,512): 128 floats (interleaved)
    float* sW1   = (float*)(smem + 512);      // 64 floats W1[hBase+1 ..]
    float* sEps  = (float*)(smem + 768);      // 64 floats
    const uint32_t TB = sb + 1024;

    const int tid  = threadIdx.x;
    const int lane = tid & 31;
    const int warp = tid >> 5;
    const int wm = warp >> 2;                 // 0..1
    const int wn = warp & 3;                  // 0..3
    const int rowBase = blockIdx.y * 128;
    const int colBase = blockIdx.x * 128;
    const int hBase   = blockIdx.x * 64;

    if (tid < 128)                  sw512[tid]       = g_w512[colBase + tid];
    else if (tid < 192)             sW1[tid - 128]   = W1[hBase + (tid - 128) + 1];
    else                            sEps[tid - 192]  = eps[tid - 192];

    // hoisted epilogue operands
    float xv[8];
    #pragma unroll
    for (int mi = 0; mi < 4; mi++) {
        int r = rowBase + wm * 64 + mi * 16 + (lane >> 2);
        xv[2 * mi]     = g_x512[r];
        xv[2 * mi + 1] = g_x512[r + 8];
    }

    float acc[4][4][4];
    #pragma unroll
    for (int mi = 0; mi < 4; mi++)
        #pragma unroll
        for (int nj = 0; nj < 4; nj++)
            #pragma unroll
            for (int q = 0; q < 4; q++)
                acc[mi][nj][q] = 0.0f;

    auto issue_chunk = [&](int c, int buf) {
        const uint32_t tb = TB + buf * CHSET_B;
        #pragma unroll
        for (int t = 0; t < 2; t++) {
            const char* gbase = t ? (const char*)g_b16 : (const char*)g_x16;
            const int rbase = t ? colBase : rowBase;
            #pragma unroll
            for (int i = 0; i < 4; i++) {
                int q = tid + i * 256;        // 0..1023 : 128 rows x 8 16B-slots
                int r = q >> 3, s = q & 7;
                const char* gp = gbase + (size_t)(rbase + r) * (KP * 2)
                               + c * BKB + s * 16;
                uint32_t sp = tb + t * TILE_B + SW128(r * BKB + s * 16);
                asm volatile("cp.async.cg.shared.global [%0], [%1], 16;"
                             :: "r"(sp), "l"(gp));
            }
        }
        asm volatile("cp.async.commit_group;" ::: "memory");
    };

    issue_chunk(0, 0);
    issue_chunk(1, 1);

    #pragma unroll
    for (int c = 0; c < NCHUNK; c++) {
        const int buf = c % NSTAGE;           // constant after unroll

        if (c < NCHUNK - 1) {
            asm volatile("cp.async.wait_group 1;" ::: "memory");
        } else {
            asm volatile("cp.async.wait_group 0;" ::: "memory");
        }
        __syncthreads();
        if (c + 2 < NCHUNK)
            issue_chunk(c + 2, (c + 2) % NSTAGE);

        const uint32_t Ah = TB + buf * CHSET_B;
        const uint32_t Bh = Ah + TILE_B;

        #pragma unroll
        for (int s = 0; s < 4; s++) {
            const int k0 = s * 16;
            uint32_t ah[4][4], bhf[4][2];

            #pragma unroll
            for (int mi = 0; mi < 4; mi++) {
                int row = wm * 64 + mi * 16 + (lane & 15);
                int col = k0 + ((lane >> 4) << 3);
                uint32_t off = SW128(row * BKB + col * 2);
                LDSM_X4(ah[mi], Ah + off);
            }
            #pragma unroll
            for (int p = 0; p < 2; p++) {
                int row = wn * 32 + p * 16 + (lane & 7) + ((lane & 16) >> 1);
                int col = k0 + (lane & 8);
                uint32_t off = SW128(row * BKB + col * 2);
                uint32_t r[4];
                LDSM_X4(r, Bh + off);
                bhf[p * 2][0] = r[0]; bhf[p * 2][1] = r[1];
                bhf[p * 2 + 1][0] = r[2]; bhf[p * 2 + 1][1] = r[3];
            }

            #pragma unroll
            for (int mi = 0; mi < 4; mi++)
                #pragma unroll
                for (int nj = 0; nj < 4; nj++)
                    MMA16816F16(acc[mi][nj], ah[mi], bhf[nj]);
        }
    }

    // ---- stage (a,b) pairs into smem (reuse pipeline region) ----
    __syncthreads();                     // all MMA smem reads done

    float* AB = (float*)(smem + 1024);   // [row][ABSTRIDE]: (a,b) x 64 h
    #pragma unroll
    for (int mi = 0; mi < 4; mi++) {
        int r0 = wm * 64 + mi * 16 + (lane >> 2);
        #pragma unroll
        for (int nj = 0; nj < 4; nj++) {
            int h = wn * 16 + nj * 4 + (lane & 3);
            float wmv = sw512[2 * h], wsv = sw512[2 * h + 1];
            float2 v0 = { acc[mi][nj][0] + xv[2 * mi] * wmv,
                          acc[mi][nj][1] + xv[2 * mi] * wsv };
            float2 v1 = { acc[mi][nj][2] + xv[2 * mi + 1] * wmv,
                          acc[mi][nj][3] + xv[2 * mi + 1] * wsv };
            *(float2*)&AB[r0 * ABSTRIDE + 2 * h]       = v0;
            *(float2*)&AB[(r0 + 8) * ABSTRIDE + 2 * h] = v1;
        }
    }
    __syncthreads();

    // ---- fused MC epilogue: thread = (row, mc-half) ----
    const int row = tid >> 1;
    const int g   = tid & 1;

    ull e2[16];
    #pragma unroll
    for (int j = 0; j < 16; j++)
        e2[j] = ((const ull*)(sEps + g * 32))[j];

    ull acc2[16];
    #pragma unroll
    for (int j = 0; j < 16; j++) acc2[j] = 0ull;

    const float* abrow = &AB[row * ABSTRIDE];

    #pragma unroll 2
    for (int h2 = 0; h2 < 32; h2++) {            // two h per iteration
        float4 ab = *(const float4*)&abrow[4 * h2];      // a0,b0,a1,b1
        float2 ww = *(const float2*)&sW1[2 * h2];
        ull a0d = pk2(ab.x, ab.x), b0d = pk2(ab.y, ab.y);
        ull a1d = pk2(ab.z, ab.z), b1d = pk2(ab.w, ab.w);
        ull w0d = pk2(ww.x, ww.x), w1d = pk2(ww.y, ww.y);
        #pragma unroll
        for (int j = 0; j < 16; j++) {
            F2U t; t.u = fma2(e2[j], b0d, a0d);
            t.f.x = fmaxf(t.f.x, 0.0f); t.f.y = fmaxf(t.f.y, 0.0f);
            acc2[j] = fma2(t.u, w0d, acc2[j]);
            F2U s; s.u = fma2(e2[j], b1d, a1d);
            s.f.x = fmaxf(s.f.x, 0.0f); s.f.y = fmaxf(s.f.y, 0.0f);
            acc2[j] = fma2(s.u, w1d, acc2[j]);
        }
    }

    // partial -> SMEM (this CTA's h-quarter contribution, 128 rows x 64 mc)
    float* P = (float*)(smem + PB_OFF) + row * N_MC + g * 32;
    #pragma unroll
    for (int q = 0; q < 8; q++) {
        F2U lo, hi; lo.u = acc2[2 * q]; hi.u = acc2[2 * q + 1];
        float4 o = { lo.f.x, lo.f.y, hi.f.x, hi.f.y };
        *(float4*)(P + 4 * q) = o;
    }

    // ---- cluster DSMEM reduce: rank r outputs rows [32r, 32r+32) ----------
    CLUSTER_ARRIVE();                    // release: my P writes visible
    CLUSTER_WAIT();                      // acquire: all peers' P visible

    const uint32_t rank = blockIdx.x;    // cluster spans x: rank == bx
    const uint32_t sP   = sb + PB_OFF;
    const float w0 = W1[0];
    float4* OP = (float4*)out_pred;
    #pragma unroll
    for (int k = 0; k < 2; k++) {
        int p4 = rank * 512 + tid + k * 256;       // float4 idx in P
        uint32_t addr = sP + p4 * 16;
        float4 a = dsmem_ld4(addr, 0);
        float4 b = dsmem_ld4(addr, 1);
        float4 c = dsmem_ld4(addr, 2);
        float4 d = dsmem_ld4(addr, 3);
        float4 o;
        o.x = w0 + ((a.x + b.x) + (c.x + d.x));
        o.y = w0 + ((a.y + b.y) + (c.y + d.y));
        o.z = w0 + ((a.z + b.z) + (c.z + d.z));
        o.w = w0 + ((a.w + b.w) + (c.w + d.w));
        OP[rowBase * 16 + p4] = o;
    }

    CLUSTER_ARRIVE();                    // keep peer smem alive until all read
    CLUSTER_WAIT();
}

// ---------------------------------------------------------------------------
extern "C" void kernel_launch(void* const* d_in, const int* in_sizes, int n_in,
                              void* d_out, int out_size) {
    const float* params = (const float*)d_in[0];
    const float* W1     = (const float*)d_in[1];
    const float* x      = (const float*)d_in[2];
    const float* eps    = (const float*)d_in[3];

    float* out      = (float*)d_out;
    float* out_pred = out;
    float* out_m    = out + NROWS * N_MC;
    float* out_v    = out_m + LEN_M;

    cudaFuncSetAttribute(gemm_fused, cudaFuncAttributeMaxDynamicSharedMemorySize, GSMEM);

    prep_all<<<XBLK0 + NROWS / 4, 256>>>(params, x, out_m, out_v);
    gemm_fused<<<dim3(4, 32), 256, GSMEM>>>(W1, eps, out_pred);
}